// round 7
// baseline (speedup 1.0000x reference)
#include <cuda_runtime.h>
#include <cstdint>

// Problem dims
#define BB   64
#define SS   512
#define NHH  4
#define DD   256
#define HH   256
#define MROWS (BB*SS*NHH)   // 131072

// ---------------- device scratch (static, allocation-free) ----------------
__device__ float g_kxW[(size_t)MROWS * 256];   // x @ (Wk@Wcomb)   (no bias)
__device__ float g_xW1[(size_t)MROWS * 256];   // x @ W1_top       (no bias)
__device__ float g_kscore[MROWS];
__device__ float g_Wcomb[256 * 256];           // Wproj @ W1_bot
__device__ float g_Wbig[256 * 512];            // [Wk@Wcomb | W1_top]  (K=256 rows, N=512)
__device__ float g_WbigD[256 * 1024];          // duplicated pairs: [k][2n]=[k][2n+1]=Wbig[k][n]
__device__ float g_bias[512];                  // [bk@Wcomb | b1 + bproj@W1bot]
__device__ float g_vq[256];                    // Wq @ w2
__device__ float g_wk1[256];                   // Wk @ w1
__device__ float g_w2v[256];                   // W2 @ vq
__device__ float g_scalars[4];                 // [cq, ck1, c2+cq]
__device__ float g_h1[BB * NHH * 256];
__device__ float g_hidden[BB * NHH * 256];

// ---------------- helpers ----------------
__device__ __forceinline__ uint32_t smem_u32(const void* p) {
    uint32_t a;
    asm("{ .reg .u64 t; cvta.to.shared.u64 t, %1; cvt.u32.u64 %0, t; }" : "=r"(a) : "l"(p));
    return a;
}
__device__ __forceinline__ void cpa16(void* s, const void* g) {
    uint32_t sa = smem_u32(s);
    asm volatile("cp.async.cg.shared.global [%0], [%1], 16;" :: "r"(sa), "l"(g));
}
// packed fp32x2 FMA (Blackwell): acc.{lo,hi} += a.{lo,hi} * b.{lo,hi}
#define FFMA2(acc, a, b) \
    asm("fma.rn.f32x2 %0, %1, %2, %0;" : "+l"(acc) : "l"(a), "l"(b))
__device__ __forceinline__ float lo32(unsigned long long v) { return __uint_as_float((unsigned)v); }
__device__ __forceinline__ float hi32(unsigned long long v) { return __uint_as_float((unsigned)(v >> 32)); }
__device__ __forceinline__ float tanh_ap(float x) {
    float y; asm("tanh.approx.f32 %0, %1;" : "=f"(y) : "f"(x)); return y;
}
__device__ __forceinline__ float rcp_ap(float x) {
    float y; asm("rcp.approx.f32 %0, %1;" : "=f"(y) : "f"(x)); return y;
}
// 16B-block swizzle within a 1KB Bs row: XOR bit4 with bit7
#define SWZ(o) ((o) ^ ((((o) >> 7) & 1) << 4))

// ---------------- small setup kernels ----------------
__global__ void k_setup1(const float* __restrict__ Wk, const float* __restrict__ bk,
                         const float* __restrict__ Wq, const float* __restrict__ bq,
                         const float* __restrict__ w_mlp) {
    __shared__ float sw1[256], sw2[256];
    int tid = threadIdx.x;
    sw1[tid] = w_mlp[tid];
    sw2[tid] = w_mlp[256 + tid];
    __syncthreads();
    float vq = 0.f, wk1 = 0.f;
    for (int h = 0; h < 256; h++) {
        vq  += Wq[tid * 256 + h] * sw2[h];
        wk1 += Wk[tid * 256 + h] * sw1[h];
    }
    g_vq[tid] = vq;
    g_wk1[tid] = wk1;
    if (tid == 0) {
        float cq = 0.f, ck1 = 0.f;
        for (int h = 0; h < 256; h++) { cq += bq[h] * sw2[h]; ck1 += bk[h] * sw1[h]; }
        g_scalars[0] = cq;
        g_scalars[1] = ck1;
    }
}

__global__ void k_wcomb(const float* __restrict__ Wproj, const float* __restrict__ W1) {
    __shared__ float sp[256];
    int h = blockIdx.x, tid = threadIdx.x;
    sp[tid] = Wproj[h * 256 + tid];
    __syncthreads();
    float acc = 0.f;
    for (int hp = 0; hp < 256; hp++)
        acc += sp[hp] * W1[(256 + hp) * 256 + tid];
    g_Wcomb[h * 256 + tid] = acc;
}

__global__ void k_wkc(const float* __restrict__ Wk, const float* __restrict__ W1,
                      const float* __restrict__ bk, const float* __restrict__ b1,
                      const float* __restrict__ bproj, const float* __restrict__ W2,
                      const float* __restrict__ b2) {
    int tid = threadIdx.x;
    if (blockIdx.x < 256) {
        int d = blockIdx.x;
        __shared__ float s[256];
        s[tid] = Wk[d * 256 + tid];
        __syncthreads();
        float acc = 0.f;
        for (int h = 0; h < 256; h++) acc += s[h] * g_Wcomb[h * 256 + tid];
        g_Wbig[d * 512 + tid]       = acc;
        g_Wbig[d * 512 + 256 + tid] = W1[d * 256 + tid];
    } else {
        float a = 0.f, bb = 0.f, w = 0.f;
        for (int h = 0; h < 256; h++) a  += bk[h]    * g_Wcomb[h * 256 + tid];
        for (int h = 0; h < 256; h++) bb += bproj[h] * W1[(256 + h) * 256 + tid];
        for (int h = 0; h < 256; h++) w  += W2[tid * 256 + h] * g_vq[h];
        g_bias[tid]       = a;
        g_bias[256 + tid] = b1[tid] + bb;
        g_w2v[tid] = w;
        if (tid == 0) {
            float c2 = 0.f;
            for (int h = 0; h < 256; h++) c2 += b2[h] * g_vq[h];
            g_scalars[2] = c2 + g_scalars[0];
        }
    }
}

// duplicate Wbig pairs for direct FFMA2 operand loads
__global__ void k_dupB() {
    int idx = blockIdx.x * 256 + threadIdx.x;   // 131072
    int k = idx >> 9, n = idx & 511;
    float v = g_Wbig[k * 512 + n];
    g_WbigD[k * 1024 + 2 * n]     = v;
    g_WbigD[k * 1024 + 2 * n + 1] = v;
}

// ---------------- GEMM v3: C(131072x512) = X(131072x256) @ g_Wbig(256x512)
// fp32 SIMT, packed f32x2 FMA, B pre-duplicated (no dup movs), swizzled Bs.
// BM=128 BN=128 BK=8, 128 threads, thread tile TM=16 x TN=8. kscore fused.
__global__ void __launch_bounds__(128) k_gemm3(const float* __restrict__ A) {
    __shared__ float As[2][8][128];   // [k][m] transposed
    __shared__ float Bs[2][8][256];   // [k][dup n] swizzled 16B blocks
    __shared__ float swk[256];
    const int nb = blockIdx.x;   // 0..3
    const int rb = blockIdx.y;   // 0..1023
    const int tid = threadIdx.x;
    const int tx = tid & 15, ty = tid >> 4;
    const float* Ab = A + (size_t)rb * 128 * 256 + (size_t)tid * 256;
    const int kRow = tid >> 4, cSeg = (tid & 15) * 64;   // B store: row, byte base

    swk[tid] = g_wk1[tid];
    swk[tid + 128] = g_wk1[tid + 128];

    // per-thread swizzled read offsets (bytes within a 1KB Bs row)
    const uint32_t so0 = SWZ((uint32_t)(tx * 32));
    const uint32_t so1 = SWZ((uint32_t)(tx * 32 + 16));
    const uint32_t so2 = SWZ((uint32_t)(512 + tx * 32));
    const uint32_t so3 = SWZ((uint32_t)(512 + tx * 32 + 16));

    unsigned long long acc[8][8];
#pragma unroll
    for (int i = 0; i < 8; i++)
#pragma unroll
        for (int j = 0; j < 8; j++) acc[i][j] = 0ull;

    float rA[8];
    float kdot = 0.f;

    auto ldgA = [&](int kc) {
        float4 u = *(const float4*)(Ab + kc * 8);
        float4 v = *(const float4*)(Ab + kc * 8 + 4);
        rA[0] = u.x; rA[1] = u.y; rA[2] = u.z; rA[3] = u.w;
        rA[4] = v.x; rA[5] = v.y; rA[6] = v.z; rA[7] = v.w;
    };
    auto stsA = [&](int buf) {
#pragma unroll
        for (int kk = 0; kk < 8; kk++) As[buf][kk][tid] = rA[kk];
    };
    auto cpB = [&](int kc, int buf) {
        const char* src = (const char*)(g_WbigD + (size_t)(kc * 8 + kRow) * 1024 + nb * 256);
        char* dstRow = (char*)&Bs[buf][kRow][0];
#pragma unroll
        for (int j = 0; j < 4; j++) {
            uint32_t o = (uint32_t)(cSeg + j * 16);
            cpa16(dstRow + SWZ(o), src + o);
        }
    };

    // prologue
    ldgA(0); stsA(0); cpB(0, 0);
    asm volatile("cp.async.commit_group;" ::: "memory");
    ldgA(1);

#pragma unroll 1
    for (int kc = 0; kc < 32; kc++) {
        const int buf = kc & 1;
        asm volatile("cp.async.wait_group 0;" ::: "memory");
        __syncthreads();
        if (kc + 1 < 32) {
            cpB(kc + 1, buf ^ 1);
            asm volatile("cp.async.commit_group;" ::: "memory");
            stsA(buf ^ 1);
        }
        if (kc + 2 < 32) ldgA(kc + 2);

        // fused kscore partial (this thread's row lives in As[.][.][tid])
#pragma unroll
        for (int k = 0; k < 8; k++) kdot += As[buf][k][tid] * swk[kc * 8 + k];

#pragma unroll
        for (int k = 0; k < 8; k++) {
            const ulonglong2* pm = (const ulonglong2*)&As[buf][k][ty * 16];
            ulonglong2 m0 = pm[0], m1 = pm[1], m2 = pm[2], m3 = pm[3];
            unsigned long long a[8] = {m0.x, m0.y, m1.x, m1.y, m2.x, m2.y, m3.x, m3.y};
            const char* rowB = (const char*)&Bs[buf][k][0];
            ulonglong2 q0 = *(const ulonglong2*)(rowB + so0);
            ulonglong2 q1 = *(const ulonglong2*)(rowB + so1);
            ulonglong2 q2 = *(const ulonglong2*)(rowB + so2);
            ulonglong2 q3 = *(const ulonglong2*)(rowB + so3);
            unsigned long long d[8] = {q0.x, q0.y, q1.x, q1.y, q2.x, q2.y, q3.x, q3.y};
#pragma unroll
            for (int mp = 0; mp < 8; mp++)
#pragma unroll
                for (int j = 0; j < 8; j++)
                    FFMA2(acc[mp][j], a[mp], d[j]);
        }
    }

    if (nb == 0) g_kscore[(size_t)rb * 128 + tid] = kdot + g_scalars[1];

    float* Cout = (nb < 2) ? g_kxW : g_xW1;
    const int colbase = (nb & 1) * 128;
#pragma unroll
    for (int mp = 0; mp < 8; mp++) {
        size_t r = (size_t)rb * 128 + ty * 16 + 2 * mp;
        float4 v;
        v.x = lo32(acc[mp][0]); v.y = lo32(acc[mp][1]); v.z = lo32(acc[mp][2]); v.w = lo32(acc[mp][3]);
        *(float4*)&Cout[r * 256 + colbase + tx * 4] = v;
        v.x = lo32(acc[mp][4]); v.y = lo32(acc[mp][5]); v.z = lo32(acc[mp][6]); v.w = lo32(acc[mp][7]);
        *(float4*)&Cout[r * 256 + colbase + 64 + tx * 4] = v;
        v.x = hi32(acc[mp][0]); v.y = hi32(acc[mp][1]); v.z = hi32(acc[mp][2]); v.w = hi32(acc[mp][3]);
        *(float4*)&Cout[(r + 1) * 256 + colbase + tx * 4] = v;
        v.x = hi32(acc[mp][4]); v.y = hi32(acc[mp][5]); v.z = hi32(acc[mp][6]); v.w = hi32(acc[mp][7]);
        *(float4*)&Cout[(r + 1) * 256 + colbase + 64 + tx * 4] = v;
    }
}

// ---------------- recurrent scan v3: one warp per (b, i), approx ops -----------
__global__ void __launch_bounds__(32) k_recur2() {
    __shared__ __align__(16) float4 sbuf[4][324];
    const int cta = blockIdx.x;
    const int b = cta >> 2, i = cta & 3;
    const int lane = threadIdx.x;

    float4 wva = *(const float4*)(g_w2v + lane * 4);
    float4 wvb = *(const float4*)(g_w2v + 128 + lane * 4);
    float4 cba, cbb;
    {
        float4 bka = *(const float4*)(g_bias + lane * 4);
        float4 bkb = *(const float4*)(g_bias + 128 + lane * 4);
        float4 bxa = *(const float4*)(g_bias + 256 + lane * 4);
        float4 bxb = *(const float4*)(g_bias + 256 + 128 + lane * 4);
        cba.x = bka.x + bxa.x; cba.y = bka.y + bxa.y; cba.z = bka.z + bxa.z; cba.w = bka.w + bxa.w;
        cbb.x = bkb.x + bxb.x; cbb.y = bkb.y + bxb.y; cbb.z = bkb.z + bxb.z; cbb.w = bkb.w + bxb.w;
    }
    const float c2 = g_scalars[2];
    float qs = g_scalars[0];

    auto issue = [&](int t, int s) {
        const float4* kxg = (const float4*)(g_kxW + ((size_t)(b * 512 + t) * 4) * 256);
        const float4* sxg = (const float4*)(g_xW1 + ((size_t)((b * 512 + t) * 4 + i)) * 256);
        float4* st = sbuf[s];
#pragma unroll
        for (int u = 0; u < 8; u++) cpa16(&st[lane + u * 32], kxg + lane + u * 32);
        cpa16(&st[256 + lane * 2], sxg + lane * 2);
        cpa16(&st[256 + lane * 2 + 1], sxg + lane * 2 + 1);
        if (lane == 0) cpa16(&st[320], g_kscore + (size_t)(b * 512 + t) * 4);
        asm volatile("cp.async.commit_group;" ::: "memory");
    };

    issue(0, 0); issue(1, 1); issue(2, 2); issue(3, 3);

    for (int t = 0; t < 512; t++) {
        const int s = t & 3;
        asm volatile("cp.async.wait_group 3;" ::: "memory");
        __syncwarp();

        const float4* st = sbuf[s];
        float4 k0a = st[lane],        k0b = st[32 + lane];
        float4 k1a = st[64 + lane],   k1b = st[96 + lane];
        float4 k2a = st[128 + lane],  k2b = st[160 + lane];
        float4 k3a = st[192 + lane],  k3b = st[224 + lane];
        float4 sxa = st[256 + lane],  sxb = st[288 + lane];
        float4 ks4 = st[320];
        __syncwarp();

        // prefetch t+4 into this (now register-held) slot before compute
        if (t + 4 < 512) issue(t + 4, s);

        // 4-way softmax of approx-tanh scores, redundant in every lane
        float s0 = tanh_ap(qs + ks4.x), s1 = tanh_ap(qs + ks4.y);
        float s2 = tanh_ap(qs + ks4.z), s3 = tanh_ap(qs + ks4.w);
        float mx = fmaxf(fmaxf(s0, s1), fmaxf(s2, s3));
        float e0 = __expf(s0 - mx), e1 = __expf(s1 - mx);
        float e2 = __expf(s2 - mx), e3 = __expf(s3 - mx);
        float inv = rcp_ap(e0 + e1 + e2 + e3);
        float p0 = e0 * inv, p1 = e1 * inv, p2 = e2 * inv, p3 = e3 * inv;

        float4 ra, rb;
        ra.x = fmaxf(sxa.x + cba.x + (p0 * k0a.x + p1 * k1a.x) + (p2 * k2a.x + p3 * k3a.x), 0.f);
        ra.y = fmaxf(sxa.y + cba.y + (p0 * k0a.y + p1 * k1a.y) + (p2 * k2a.y + p3 * k3a.y), 0.f);
        ra.z = fmaxf(sxa.z + cba.z + (p0 * k0a.z + p1 * k1a.z) + (p2 * k2a.z + p3 * k3a.z), 0.f);
        ra.w = fmaxf(sxa.w + cba.w + (p0 * k0a.w + p1 * k1a.w) + (p2 * k2a.w + p3 * k3a.w), 0.f);
        rb.x = fmaxf(sxb.x + cbb.x + (p0 * k0b.x + p1 * k1b.x) + (p2 * k2b.x + p3 * k3b.x), 0.f);
        rb.y = fmaxf(sxb.y + cbb.y + (p0 * k0b.y + p1 * k1b.y) + (p2 * k2b.y + p3 * k3b.y), 0.f);
        rb.z = fmaxf(sxb.z + cbb.z + (p0 * k0b.z + p1 * k1b.z) + (p2 * k2b.z + p3 * k3b.z), 0.f);
        rb.w = fmaxf(sxb.w + cbb.w + (p0 * k0b.w + p1 * k1b.w) + (p2 * k2b.w + p3 * k3b.w), 0.f);

        float dA = (wva.x * ra.x + wva.y * ra.y) + (wva.z * ra.z + wva.w * ra.w);
        float dB = (wvb.x * rb.x + wvb.y * rb.y) + (wvb.z * rb.z + wvb.w * rb.w);
        float dot = dA + dB;
#pragma unroll
        for (int off = 16; off; off >>= 1) dot += __shfl_xor_sync(0xFFFFFFFFu, dot, off);
        qs = c2 + dot;

        if (t == 511) {
            float* dst = g_h1 + (size_t)(b * 4 + i) * 256;
            *(float4*)(dst + lane * 4) = ra;
            *(float4*)(dst + 128 + lane * 4) = rb;
        }
    }
}

// ---------------- epilogue ----------------
__global__ void k_hfinal(const float* __restrict__ W2, const float* __restrict__ b2,
                         float* __restrict__ out) {
    int r = blockIdx.x, tid = threadIdx.x;
    __shared__ float sh[256];
    sh[tid] = g_h1[r * 256 + tid];
    __syncthreads();
    float acc = b2[tid];
    for (int h = 0; h < 256; h++) acc += sh[h] * W2[h * 256 + tid];
    g_hidden[r * 256 + tid] = acc;
    out[192 + r * 256 + tid] = acc;
}

__global__ void k_logits(const float* __restrict__ Wo, const float* __restrict__ bo,
                         float* __restrict__ out) {
    int bidx = blockIdx.x, tid = threadIdx.x, lane = tid & 31, wid = tid >> 5;
    __shared__ float red[4][3];
    float p0 = 0.f, p1 = 0.f, p2 = 0.f;
    for (int k = tid; k < 1024; k += 128) {
        float h = g_hidden[bidx * 1024 + k];
        p0 += h * Wo[k * 3 + 0];
        p1 += h * Wo[k * 3 + 1];
        p2 += h * Wo[k * 3 + 2];
    }
#pragma unroll
    for (int off = 16; off; off >>= 1) {
        p0 += __shfl_down_sync(0xFFFFFFFFu, p0, off);
        p1 += __shfl_down_sync(0xFFFFFFFFu, p1, off);
        p2 += __shfl_down_sync(0xFFFFFFFFu, p2, off);
    }
    if (lane == 0) { red[wid][0] = p0; red[wid][1] = p1; red[wid][2] = p2; }
    __syncthreads();
    if (tid == 0) {
        float l0 = bo[0], l1 = bo[1], l2 = bo[2];
        for (int w = 0; w < 4; w++) { l0 += red[w][0]; l1 += red[w][1]; l2 += red[w][2]; }
        float m = fmaxf(l0, fmaxf(l1, l2));
        float lse = m + logf(expf(l0 - m) + expf(l1 - m) + expf(l2 - m));
        out[bidx * 3 + 0] = l0 - lse;
        out[bidx * 3 + 1] = l1 - lse;
        out[bidx * 3 + 2] = l2 - lse;
    }
}

// ---------------- launch ----------------
extern "C" void kernel_launch(void* const* d_in, const int* in_sizes, int n_in,
                              void* d_out, int out_size) {
    const float* x     = (const float*)d_in[0];
    const float* Wk    = (const float*)d_in[1];
    const float* bk    = (const float*)d_in[2];
    const float* Wq    = (const float*)d_in[3];
    const float* bq    = (const float*)d_in[4];
    const float* w_mlp = (const float*)d_in[5];
    const float* Wproj = (const float*)d_in[6];
    const float* bproj = (const float*)d_in[7];
    const float* W1    = (const float*)d_in[8];
    const float* b1    = (const float*)d_in[9];
    const float* W2    = (const float*)d_in[10];
    const float* b2    = (const float*)d_in[11];
    const float* Wo    = (const float*)d_in[12];
    const float* bo    = (const float*)d_in[13];
    float* out = (float*)d_out;

    k_setup1<<<1, 256>>>(Wk, bk, Wq, bq, w_mlp);
    k_wcomb<<<256, 256>>>(Wproj, W1);
    k_wkc<<<257, 256>>>(Wk, W1, bk, b1, bproj, W2, b2);
    k_dupB<<<512, 256>>>();
    k_gemm3<<<dim3(4, 1024), 128>>>(x);
    k_recur2<<<256, 32>>>();
    k_hfinal<<<256, 256>>>(W2, b2, out);
    k_logits<<<64, 128>>>(Wo, bo, out);
}

// round 10
// speedup vs baseline: 1.1026x; 1.1026x over previous
#include <cuda_runtime.h>
#include <cstdint>

// Problem dims
#define BB   64
#define SS   512
#define NHH  4
#define DD   256
#define HH   256
#define MROWS (BB*SS*NHH)   // 131072

// ---------------- device scratch (static, allocation-free) ----------------
__device__ float g_kxW[(size_t)MROWS * 256];   // x @ (Wk@Wcomb)   (no bias)
__device__ float g_xW1[(size_t)MROWS * 256];   // x @ W1_top       (no bias)
__device__ float g_kscore[MROWS];
__device__ float g_Wcomb[256 * 256];           // Wproj @ W1_bot
__device__ float g_Wbig[256 * 512];            // [Wk@Wcomb | W1_top]  (K=256 rows, N=512)
__device__ float g_bias[512];                  // [bk@Wcomb | b1 + bproj@W1bot]
__device__ float g_vq[256];                    // Wq @ w2
__device__ float g_wk1[256];                   // Wk @ w1
__device__ float g_w2v[256];                   // W2 @ vq
__device__ float g_scalars[4];                 // [cq, ck1, c2+cq]
__device__ float g_h1[BB * NHH * 256];
__device__ float g_hidden[BB * NHH * 256];

// ---------------- helpers ----------------
__device__ __forceinline__ uint32_t smem_u32(const void* p) {
    uint32_t a;
    asm("{ .reg .u64 t; cvta.to.shared.u64 t, %1; cvt.u32.u64 %0, t; }" : "=r"(a) : "l"(p));
    return a;
}
__device__ __forceinline__ void cpa16(void* s, const void* g) {
    uint32_t sa = smem_u32(s);
    asm volatile("cp.async.cg.shared.global [%0], [%1], 16;" :: "r"(sa), "l"(g));
}
// packed fp32x2 FMA (Blackwell): acc.{lo,hi} += a.{lo,hi} * b.{lo,hi}
#define FFMA2(acc, a, b) \
    asm("fma.rn.f32x2 %0, %1, %2, %0;" : "+l"(acc) : "l"(a), "l"(b))
__device__ __forceinline__ unsigned long long dup2(float x) {
    unsigned long long d;
    asm("mov.b64 %0, {%1, %1};" : "=l"(d) : "f"(x));
    return d;
}
__device__ __forceinline__ float lo32(unsigned long long v) { return __uint_as_float((unsigned)v); }
__device__ __forceinline__ float hi32(unsigned long long v) { return __uint_as_float((unsigned)(v >> 32)); }
__device__ __forceinline__ float tanh_ap(float x) {
    float y; asm("tanh.approx.f32 %0, %1;" : "=f"(y) : "f"(x)); return y;
}
__device__ __forceinline__ float rcp_ap(float x) {
    float y; asm("rcp.approx.f32 %0, %1;" : "=f"(y) : "f"(x)); return y;
}

// ---------------- small setup kernels ----------------
__global__ void k_setup1(const float* __restrict__ Wk, const float* __restrict__ bk,
                         const float* __restrict__ Wq, const float* __restrict__ bq,
                         const float* __restrict__ w_mlp) {
    __shared__ float sw1[256], sw2[256];
    int tid = threadIdx.x;
    sw1[tid] = w_mlp[tid];
    sw2[tid] = w_mlp[256 + tid];
    __syncthreads();
    float vq = 0.f, wk1 = 0.f;
    for (int h = 0; h < 256; h++) {
        vq  += Wq[tid * 256 + h] * sw2[h];
        wk1 += Wk[tid * 256 + h] * sw1[h];
    }
    g_vq[tid] = vq;
    g_wk1[tid] = wk1;
    if (tid == 0) {
        float cq = 0.f, ck1 = 0.f;
        for (int h = 0; h < 256; h++) { cq += bq[h] * sw2[h]; ck1 += bk[h] * sw1[h]; }
        g_scalars[0] = cq;
        g_scalars[1] = ck1;
    }
}

__global__ void k_wcomb(const float* __restrict__ Wproj, const float* __restrict__ W1) {
    __shared__ float sp[256];
    int h = blockIdx.x, tid = threadIdx.x;
    sp[tid] = Wproj[h * 256 + tid];
    __syncthreads();
    float acc = 0.f;
    for (int hp = 0; hp < 256; hp++)
        acc += sp[hp] * W1[(256 + hp) * 256 + tid];
    g_Wcomb[h * 256 + tid] = acc;
}

__global__ void k_wkc(const float* __restrict__ Wk, const float* __restrict__ W1,
                      const float* __restrict__ bk, const float* __restrict__ b1,
                      const float* __restrict__ bproj, const float* __restrict__ W2,
                      const float* __restrict__ b2) {
    int tid = threadIdx.x;
    if (blockIdx.x < 256) {
        int d = blockIdx.x;
        __shared__ float s[256];
        s[tid] = Wk[d * 256 + tid];
        __syncthreads();
        float acc = 0.f;
        for (int h = 0; h < 256; h++) acc += s[h] * g_Wcomb[h * 256 + tid];
        g_Wbig[d * 512 + tid]       = acc;
        g_Wbig[d * 512 + 256 + tid] = W1[d * 256 + tid];
    } else {
        float a = 0.f, bb = 0.f, w = 0.f;
        for (int h = 0; h < 256; h++) a  += bk[h]    * g_Wcomb[h * 256 + tid];
        for (int h = 0; h < 256; h++) bb += bproj[h] * W1[(256 + h) * 256 + tid];
        for (int h = 0; h < 256; h++) w  += W2[tid * 256 + h] * g_vq[h];
        g_bias[tid]       = a;
        g_bias[256 + tid] = b1[tid] + bb;
        g_w2v[tid] = w;
        if (tid == 0) {
            float c2 = 0.f;
            for (int h = 0; h < 256; h++) c2 += b2[h] * g_vq[h];
            g_scalars[2] = c2 + g_scalars[0];
        }
    }
}

// ---------------- GEMM (round-5 mainloop + fused kscore + 3-stage B) ----------
// C(131072x512) = X(131072x256) @ g_Wbig(256x512)
// fp32 SIMT packed f32x2 FMA. BM=128 BN=128 BK=8, 128 threads, TM=16 x TN=8.
__global__ void __launch_bounds__(128) k_gemm2(const float* __restrict__ A) {
    __shared__ float As[2][8][128];   // [k][m] transposed
    __shared__ float Bs[3][8][128];   // [k][n], triple-buffered
    __shared__ float swk[256];
    const int nb = blockIdx.x;   // 0..3
    const int rb = blockIdx.y;   // 0..1023
    const int tid = threadIdx.x;
    const int tx = tid & 15, ty = tid >> 4;
    const float* Ab = A + (size_t)rb * 128 * 256 + (size_t)tid * 256;
    const float* Bb = g_Wbig + nb * 128;
    const int kRow = tid >> 4, colB = (tid & 15) * 8;

    swk[tid]       = g_wk1[tid];
    swk[tid + 128] = g_wk1[tid + 128];   // <-- the round-9 bug: this line was missing

    unsigned long long acc[8][8];
#pragma unroll
    for (int i = 0; i < 8; i++)
#pragma unroll
        for (int j = 0; j < 8; j++) acc[i][j] = 0ull;

    float rA[8];
    float kdot = 0.f;

    auto ldgA = [&](int kc) {
        float4 u = *(const float4*)(Ab + kc * 8);
        float4 v = *(const float4*)(Ab + kc * 8 + 4);
        rA[0] = u.x; rA[1] = u.y; rA[2] = u.z; rA[3] = u.w;
        rA[4] = v.x; rA[5] = v.y; rA[6] = v.z; rA[7] = v.w;
    };
    auto stsA = [&](int buf) {
#pragma unroll
        for (int kk = 0; kk < 8; kk++) As[buf][kk][tid] = rA[kk];
    };
    auto cpB = [&](int kc, int buf) {
        const float* src = Bb + (size_t)(kc * 8 + kRow) * 512 + colB;
        cpa16(&Bs[buf][kRow][colB], src);
        cpa16(&Bs[buf][kRow][colB + 4], src + 4);
    };

    // prologue: A stage 0 staged, B stages 0 and 1 in flight
    ldgA(0); stsA(0);
    cpB(0, 0);
    asm volatile("cp.async.commit_group;" ::: "memory");
    cpB(1, 1);
    asm volatile("cp.async.commit_group;" ::: "memory");
    ldgA(1);

#pragma unroll 1
    for (int kc = 0; kc < 32; kc++) {
        const int bufA = kc & 1;
        const int bufB = kc - (kc / 3) * 3;   // kc % 3
        if (kc < 31) asm volatile("cp.async.wait_group 1;" ::: "memory");
        else         asm volatile("cp.async.wait_group 0;" ::: "memory");
        __syncthreads();
        if (kc + 2 < 32) {
            int nB = (kc + 2) - ((kc + 2) / 3) * 3;
            cpB(kc + 2, nB);
            asm volatile("cp.async.commit_group;" ::: "memory");
        }
        if (kc + 1 < 32) stsA(bufA ^ 1);
        if (kc + 2 < 32) ldgA(kc + 2);

        // fused kscore partial (this thread's own row is As[.][.][tid])
#pragma unroll
        for (int k = 0; k < 8; k++) kdot += As[bufA][k][tid] * swk[kc * 8 + k];

#pragma unroll
        for (int k = 0; k < 8; k++) {
            const ulonglong2* pm = (const ulonglong2*)&As[bufA][k][ty * 16];
            ulonglong2 m0 = pm[0], m1 = pm[1], m2 = pm[2], m3 = pm[3];
            unsigned long long a[8] = {m0.x, m0.y, m1.x, m1.y, m2.x, m2.y, m3.x, m3.y};
            float4 n0 = *(const float4*)&Bs[bufB][k][tx * 4];
            float4 n1 = *(const float4*)&Bs[bufB][k][64 + tx * 4];
            unsigned long long d[8];
            d[0] = dup2(n0.x); d[1] = dup2(n0.y); d[2] = dup2(n0.z); d[3] = dup2(n0.w);
            d[4] = dup2(n1.x); d[5] = dup2(n1.y); d[6] = dup2(n1.z); d[7] = dup2(n1.w);
#pragma unroll
            for (int mp = 0; mp < 8; mp++)
#pragma unroll
                for (int j = 0; j < 8; j++)
                    FFMA2(acc[mp][j], a[mp], d[j]);
        }
    }

    if (nb == 0) g_kscore[(size_t)rb * 128 + tid] = kdot + g_scalars[1];

    float* Cout = (nb < 2) ? g_kxW : g_xW1;
    const int colbase = (nb & 1) * 128;
#pragma unroll
    for (int mp = 0; mp < 8; mp++) {
        size_t r = (size_t)rb * 128 + ty * 16 + 2 * mp;
        float4 v;
        v.x = lo32(acc[mp][0]); v.y = lo32(acc[mp][1]); v.z = lo32(acc[mp][2]); v.w = lo32(acc[mp][3]);
        *(float4*)&Cout[r * 256 + colbase + tx * 4] = v;
        v.x = lo32(acc[mp][4]); v.y = lo32(acc[mp][5]); v.z = lo32(acc[mp][6]); v.w = lo32(acc[mp][7]);
        *(float4*)&Cout[r * 256 + colbase + 64 + tx * 4] = v;
        v.x = hi32(acc[mp][0]); v.y = hi32(acc[mp][1]); v.z = hi32(acc[mp][2]); v.w = hi32(acc[mp][3]);
        *(float4*)&Cout[(r + 1) * 256 + colbase + tx * 4] = v;
        v.x = hi32(acc[mp][4]); v.y = hi32(acc[mp][5]); v.z = hi32(acc[mp][6]); v.w = hi32(acc[mp][7]);
        *(float4*)&Cout[(r + 1) * 256 + colbase + 64 + tx * 4] = v;
    }
}

// ---------------- recurrent scan v3: one warp per (b, i), approx ops -----------
__global__ void __launch_bounds__(32) k_recur2() {
    __shared__ __align__(16) float4 sbuf[4][324];
    const int cta = blockIdx.x;
    const int b = cta >> 2, i = cta & 3;
    const int lane = threadIdx.x;

    float4 wva = *(const float4*)(g_w2v + lane * 4);
    float4 wvb = *(const float4*)(g_w2v + 128 + lane * 4);
    float4 cba, cbb;
    {
        float4 bka = *(const float4*)(g_bias + lane * 4);
        float4 bkb = *(const float4*)(g_bias + 128 + lane * 4);
        float4 bxa = *(const float4*)(g_bias + 256 + lane * 4);
        float4 bxb = *(const float4*)(g_bias + 256 + 128 + lane * 4);
        cba.x = bka.x + bxa.x; cba.y = bka.y + bxa.y; cba.z = bka.z + bxa.z; cba.w = bka.w + bxa.w;
        cbb.x = bkb.x + bxb.x; cbb.y = bkb.y + bxb.y; cbb.z = bkb.z + bxb.z; cbb.w = bkb.w + bxb.w;
    }
    const float c2 = g_scalars[2];
    float qs = g_scalars[0];

    auto issue = [&](int t, int s) {
        const float4* kxg = (const float4*)(g_kxW + ((size_t)(b * 512 + t) * 4) * 256);
        const float4* sxg = (const float4*)(g_xW1 + ((size_t)((b * 512 + t) * 4 + i)) * 256);
        float4* st = sbuf[s];
#pragma unroll
        for (int u = 0; u < 8; u++) cpa16(&st[lane + u * 32], kxg + lane + u * 32);
        cpa16(&st[256 + lane * 2], sxg + lane * 2);
        cpa16(&st[256 + lane * 2 + 1], sxg + lane * 2 + 1);
        if (lane == 0) cpa16(&st[320], g_kscore + (size_t)(b * 512 + t) * 4);
        asm volatile("cp.async.commit_group;" ::: "memory");
    };

    issue(0, 0); issue(1, 1); issue(2, 2); issue(3, 3);

    for (int t = 0; t < 512; t++) {
        const int s = t & 3;
        asm volatile("cp.async.wait_group 3;" ::: "memory");
        __syncwarp();

        const float4* st = sbuf[s];
        float4 k0a = st[lane],        k0b = st[32 + lane];
        float4 k1a = st[64 + lane],   k1b = st[96 + lane];
        float4 k2a = st[128 + lane],  k2b = st[160 + lane];
        float4 k3a = st[192 + lane],  k3b = st[224 + lane];
        float4 sxa = st[256 + lane],  sxb = st[288 + lane];
        float4 ks4 = st[320];
        __syncwarp();

        // prefetch t+4 into this (now register-held) slot before compute
        if (t + 4 < 512) issue(t + 4, s);

        float s0 = tanh_ap(qs + ks4.x), s1 = tanh_ap(qs + ks4.y);
        float s2 = tanh_ap(qs + ks4.z), s3 = tanh_ap(qs + ks4.w);
        float mx = fmaxf(fmaxf(s0, s1), fmaxf(s2, s3));
        float e0 = __expf(s0 - mx), e1 = __expf(s1 - mx);
        float e2 = __expf(s2 - mx), e3 = __expf(s3 - mx);
        float inv = rcp_ap(e0 + e1 + e2 + e3);
        float p0 = e0 * inv, p1 = e1 * inv, p2 = e2 * inv, p3 = e3 * inv;

        float4 ra, rb;
        ra.x = fmaxf(sxa.x + cba.x + (p0 * k0a.x + p1 * k1a.x) + (p2 * k2a.x + p3 * k3a.x), 0.f);
        ra.y = fmaxf(sxa.y + cba.y + (p0 * k0a.y + p1 * k1a.y) + (p2 * k2a.y + p3 * k3a.y), 0.f);
        ra.z = fmaxf(sxa.z + cba.z + (p0 * k0a.z + p1 * k1a.z) + (p2 * k2a.z + p3 * k3a.z), 0.f);
        ra.w = fmaxf(sxa.w + cba.w + (p0 * k0a.w + p1 * k1a.w) + (p2 * k2a.w + p3 * k3a.w), 0.f);
        rb.x = fmaxf(sxb.x + cbb.x + (p0 * k0b.x + p1 * k1b.x) + (p2 * k2b.x + p3 * k3b.x), 0.f);
        rb.y = fmaxf(sxb.y + cbb.y + (p0 * k0b.y + p1 * k1b.y) + (p2 * k2b.y + p3 * k3b.y), 0.f);
        rb.z = fmaxf(sxb.z + cbb.z + (p0 * k0b.z + p1 * k1b.z) + (p2 * k2b.z + p3 * k3b.z), 0.f);
        rb.w = fmaxf(sxb.w + cbb.w + (p0 * k0b.w + p1 * k1b.w) + (p2 * k2b.w + p3 * k3b.w), 0.f);

        float dA = (wva.x * ra.x + wva.y * ra.y) + (wva.z * ra.z + wva.w * ra.w);
        float dB = (wvb.x * rb.x + wvb.y * rb.y) + (wvb.z * rb.z + wvb.w * rb.w);
        float dot = dA + dB;
#pragma unroll
        for (int off = 16; off; off >>= 1) dot += __shfl_xor_sync(0xFFFFFFFFu, dot, off);
        qs = c2 + dot;

        if (t == 511) {
            float* dst = g_h1 + (size_t)(b * 4 + i) * 256;
            *(float4*)(dst + lane * 4) = ra;
            *(float4*)(dst + 128 + lane * 4) = rb;
        }
    }
}

// ---------------- epilogue ----------------
__global__ void k_hfinal(const float* __restrict__ W2, const float* __restrict__ b2,
                         float* __restrict__ out) {
    int r = blockIdx.x, tid = threadIdx.x;
    __shared__ float sh[256];
    sh[tid] = g_h1[r * 256 + tid];
    __syncthreads();
    float acc = b2[tid];
    for (int h = 0; h < 256; h++) acc += sh[h] * W2[h * 256 + tid];
    g_hidden[r * 256 + tid] = acc;
    out[192 + r * 256 + tid] = acc;
}

__global__ void k_logits(const float* __restrict__ Wo, const float* __restrict__ bo,
                         float* __restrict__ out) {
    int bidx = blockIdx.x, tid = threadIdx.x, lane = tid & 31, wid = tid >> 5;
    __shared__ float red[4][3];
    float p0 = 0.f, p1 = 0.f, p2 = 0.f;
    for (int k = tid; k < 1024; k += 128) {
        float h = g_hidden[bidx * 1024 + k];
        p0 += h * Wo[k * 3 + 0];
        p1 += h * Wo[k * 3 + 1];
        p2 += h * Wo[k * 3 + 2];
    }
#pragma unroll
    for (int off = 16; off; off >>= 1) {
        p0 += __shfl_down_sync(0xFFFFFFFFu, p0, off);
        p1 += __shfl_down_sync(0xFFFFFFFFu, p1, off);
        p2 += __shfl_down_sync(0xFFFFFFFFu, p2, off);
    }
    if (lane == 0) { red[wid][0] = p0; red[wid][1] = p1; red[wid][2] = p2; }
    __syncthreads();
    if (tid == 0) {
        float l0 = bo[0], l1 = bo[1], l2 = bo[2];
        for (int w = 0; w < 4; w++) { l0 += red[w][0]; l1 += red[w][1]; l2 += red[w][2]; }
        float m = fmaxf(l0, fmaxf(l1, l2));
        float lse = m + logf(expf(l0 - m) + expf(l1 - m) + expf(l2 - m));
        out[bidx * 3 + 0] = l0 - lse;
        out[bidx * 3 + 1] = l1 - lse;
        out[bidx * 3 + 2] = l2 - lse;
    }
}

// ---------------- launch ----------------
extern "C" void kernel_launch(void* const* d_in, const int* in_sizes, int n_in,
                              void* d_out, int out_size) {
    const float* x     = (const float*)d_in[0];
    const float* Wk    = (const float*)d_in[1];
    const float* bk    = (const float*)d_in[2];
    const float* Wq    = (const float*)d_in[3];
    const float* bq    = (const float*)d_in[4];
    const float* w_mlp = (const float*)d_in[5];
    const float* Wproj = (const float*)d_in[6];
    const float* bproj = (const float*)d_in[7];
    const float* W1    = (const float*)d_in[8];
    const float* b1    = (const float*)d_in[9];
    const float* W2    = (const float*)d_in[10];
    const float* b2    = (const float*)d_in[11];
    const float* Wo    = (const float*)d_in[12];
    const float* bo    = (const float*)d_in[13];
    float* out = (float*)d_out;

    k_setup1<<<1, 256>>>(Wk, bk, Wq, bq, w_mlp);
    k_wcomb<<<256, 256>>>(Wproj, W1);
    k_wkc<<<257, 256>>>(Wk, W1, bk, b1, bproj, W2, b2);
    k_gemm2<<<dim3(4, 1024), 128>>>(x);
    k_recur2<<<256, 32>>>();
    k_hfinal<<<256, 256>>>(W2, b2, out);
    k_logits<<<64, 128>>>(Wo, bo, out);
}

// round 12
// speedup vs baseline: 1.3024x; 1.1812x over previous
#include <cuda_runtime.h>
#include <cstdint>

// Problem dims
#define BB   64
#define SS   512
#define NHH  4
#define DD   256
#define HH   256
#define MROWS (BB*SS*NHH)   // 131072

// ---------------- device scratch (static, allocation-free) ----------------
__device__ float g_kxW[(size_t)MROWS * 256];   // x @ (Wk@Wcomb)   (no bias)
__device__ float g_xW1[(size_t)MROWS * 256];   // x @ W1_top       (no bias)
__device__ float g_kscore[MROWS];
__device__ float g_Wcomb[256 * 256];           // Wproj @ W1_bot
__device__ float g_Wbig[256 * 512];            // [Wk@Wcomb | W1_top]  (K=256 rows, N=512)
__device__ float g_bias[512];                  // [bk@Wcomb | b1 + bproj@W1bot]
__device__ float g_vq[256];                    // Wq @ w2
__device__ float g_wk1[256];                   // Wk @ w1
__device__ float g_w2v[256];                   // W2 @ vq
__device__ float g_scalars[4];                 // [cq, ck1, c2+cq]
__device__ float g_h1[BB * NHH * 256];
__device__ float g_hidden[BB * NHH * 256];

// ---------------- helpers ----------------
__device__ __forceinline__ uint32_t smem_u32(const void* p) {
    uint32_t a;
    asm("{ .reg .u64 t; cvta.to.shared.u64 t, %1; cvt.u32.u64 %0, t; }" : "=r"(a) : "l"(p));
    return a;
}
__device__ __forceinline__ void cpa16(void* s, const void* g) {
    uint32_t sa = smem_u32(s);
    asm volatile("cp.async.cg.shared.global [%0], [%1], 16;" :: "r"(sa), "l"(g));
}
// packed fp32x2 FMA (Blackwell): acc.{lo,hi} += a.{lo,hi} * b.{lo,hi}
#define FFMA2(acc, a, b) \
    asm("fma.rn.f32x2 %0, %1, %2, %0;" : "+l"(acc) : "l"(a), "l"(b))
__device__ __forceinline__ unsigned long long dup2(float x) {
    unsigned long long d;
    asm("mov.b64 %0, {%1, %1};" : "=l"(d) : "f"(x));
    return d;
}
__device__ __forceinline__ float lo32(unsigned long long v) { return __uint_as_float((unsigned)v); }
__device__ __forceinline__ float hi32(unsigned long long v) { return __uint_as_float((unsigned)(v >> 32)); }
__device__ __forceinline__ float tanh_ap(float x) {
    float y; asm("tanh.approx.f32 %0, %1;" : "=f"(y) : "f"(x)); return y;
}
__device__ __forceinline__ float rcp_ap(float x) {
    float y; asm("rcp.approx.f32 %0, %1;" : "=f"(y) : "f"(x)); return y;
}
__device__ __forceinline__ float warp_dot8(const float* __restrict__ row,
                                           const float* __restrict__ vec, int lane) {
    float4 a0 = *(const float4*)(row + lane * 8);
    float4 a1 = *(const float4*)(row + lane * 8 + 4);
    float4 v0 = *(const float4*)(vec + lane * 8);
    float4 v1 = *(const float4*)(vec + lane * 8 + 4);
    float d = a0.x * v0.x + a0.y * v0.y + a0.z * v0.z + a0.w * v0.w
            + a1.x * v1.x + a1.y * v1.y + a1.z * v1.z + a1.w * v1.w;
#pragma unroll
    for (int off = 16; off; off >>= 1) d += __shfl_xor_sync(0xFFFFFFFFu, d, off);
    return d;
}

// ---------------- setup: one warp per output element (coalesced row dots) ------
// blocks 0..255: vq[d] = Wq[d,:]·w2 ; wk1[d] = Wk[d,:]·w1.  block 256: cq, ck1.
__global__ void __launch_bounds__(32) k_setup1(const float* __restrict__ Wk,
                                               const float* __restrict__ bk,
                                               const float* __restrict__ Wq,
                                               const float* __restrict__ bq,
                                               const float* __restrict__ w_mlp) {
    const int d = blockIdx.x, lane = threadIdx.x;
    if (d < 256) {
        float vq  = warp_dot8(Wq + (size_t)d * 256, w_mlp + 256, lane);
        float wk1 = warp_dot8(Wk + (size_t)d * 256, w_mlp, lane);
        if (lane == 0) { g_vq[d] = vq; g_wk1[d] = wk1; }
    } else {
        float cq  = warp_dot8(bq, w_mlp + 256, lane);
        float ck1 = warp_dot8(bk, w_mlp, lane);
        if (lane == 0) { g_scalars[0] = cq; g_scalars[1] = ck1; }
    }
}

__global__ void k_wcomb(const float* __restrict__ Wproj, const float* __restrict__ W1) {
    __shared__ float sp[256];
    int h = blockIdx.x, tid = threadIdx.x;
    sp[tid] = Wproj[h * 256 + tid];
    __syncthreads();
    float acc = 0.f;
    for (int hp = 0; hp < 256; hp++)
        acc += sp[hp] * W1[(256 + hp) * 256 + tid];
    g_Wcomb[h * 256 + tid] = acc;
}

__global__ void k_wkc(const float* __restrict__ Wk, const float* __restrict__ W1,
                      const float* __restrict__ bk, const float* __restrict__ b1,
                      const float* __restrict__ bproj) {
    int tid = threadIdx.x;
    if (blockIdx.x < 256) {
        int d = blockIdx.x;
        __shared__ float s[256];
        s[tid] = Wk[d * 256 + tid];
        __syncthreads();
        float acc = 0.f;
        for (int h = 0; h < 256; h++) acc += s[h] * g_Wcomb[h * 256 + tid];
        g_Wbig[d * 512 + tid]       = acc;
        g_Wbig[d * 512 + 256 + tid] = W1[d * 256 + tid];
    } else {
        float a = 0.f, bb = 0.f;
        for (int h = 0; h < 256; h++) a  += bk[h]    * g_Wcomb[h * 256 + tid];
        for (int h = 0; h < 256; h++) bb += bproj[h] * W1[(256 + h) * 256 + tid];
        g_bias[tid]       = a;
        g_bias[256 + tid] = b1[tid] + bb;
    }
}

// blocks 0..255: w2v[d] = W2[d,:]·vq.  block 256: c2 = b2·vq; g_scalars[2]=c2+cq.
__global__ void __launch_bounds__(32) k_w2v(const float* __restrict__ W2,
                                            const float* __restrict__ b2) {
    const int d = blockIdx.x, lane = threadIdx.x;
    if (d < 256) {
        float w = warp_dot8(W2 + (size_t)d * 256, g_vq, lane);
        if (lane == 0) g_w2v[d] = w;
    } else {
        float c2 = warp_dot8(b2, g_vq, lane);
        if (lane == 0) g_scalars[2] = c2 + g_scalars[0];
    }
}

// ---------------- GEMM (round-5 exact): C = X @ g_Wbig --------------------------
// fp32 SIMT packed f32x2 FMA. BM=128 BN=128 BK=8, 128 threads, TM=16 x TN=8.
__global__ void __launch_bounds__(128) k_gemm2(const float* __restrict__ A) {
    __shared__ float As[2][8][128];   // [k][m] transposed
    __shared__ float Bs[2][8][128];   // [k][n]
    const int nb = blockIdx.x;   // 0..3
    const int rb = blockIdx.y;   // 0..1023
    const int tid = threadIdx.x;
    const int tx = tid & 15, ty = tid >> 4;
    const float* Ab = A + (size_t)rb * 128 * 256 + (size_t)tid * 256;
    const float* Bb = g_Wbig + nb * 128;
    const int kRow = tid >> 4, colB = (tid & 15) * 8;

    unsigned long long acc[8][8];
#pragma unroll
    for (int i = 0; i < 8; i++)
#pragma unroll
        for (int j = 0; j < 8; j++) acc[i][j] = 0ull;

    float rA[8];

    auto ldgA = [&](int kc) {
        float4 u = *(const float4*)(Ab + kc * 8);
        float4 v = *(const float4*)(Ab + kc * 8 + 4);
        rA[0] = u.x; rA[1] = u.y; rA[2] = u.z; rA[3] = u.w;
        rA[4] = v.x; rA[5] = v.y; rA[6] = v.z; rA[7] = v.w;
    };
    auto stsA = [&](int buf) {
#pragma unroll
        for (int kk = 0; kk < 8; kk++) As[buf][kk][tid] = rA[kk];
    };
    auto cpB = [&](int kc, int buf) {
        const float* src = Bb + (size_t)(kc * 8 + kRow) * 512 + colB;
        cpa16(&Bs[buf][kRow][colB], src);
        cpa16(&Bs[buf][kRow][colB + 4], src + 4);
    };

    // prologue
    ldgA(0); stsA(0); cpB(0, 0);
    asm volatile("cp.async.commit_group;" ::: "memory");
    ldgA(1);

#pragma unroll 1
    for (int kc = 0; kc < 32; kc++) {
        const int buf = kc & 1;
        asm volatile("cp.async.wait_group 0;" ::: "memory");
        __syncthreads();
        if (kc + 1 < 32) {
            cpB(kc + 1, buf ^ 1);
            asm volatile("cp.async.commit_group;" ::: "memory");
            stsA(buf ^ 1);
        }
        if (kc + 2 < 32) ldgA(kc + 2);

#pragma unroll
        for (int k = 0; k < 8; k++) {
            const ulonglong2* pm = (const ulonglong2*)&As[buf][k][ty * 16];
            ulonglong2 m0 = pm[0], m1 = pm[1], m2 = pm[2], m3 = pm[3];
            unsigned long long a[8] = {m0.x, m0.y, m1.x, m1.y, m2.x, m2.y, m3.x, m3.y};
            float4 n0 = *(const float4*)&Bs[buf][k][tx * 4];
            float4 n1 = *(const float4*)&Bs[buf][k][64 + tx * 4];
            unsigned long long d[8];
            d[0] = dup2(n0.x); d[1] = dup2(n0.y); d[2] = dup2(n0.z); d[3] = dup2(n0.w);
            d[4] = dup2(n1.x); d[5] = dup2(n1.y); d[6] = dup2(n1.z); d[7] = dup2(n1.w);
#pragma unroll
            for (int mp = 0; mp < 8; mp++)
#pragma unroll
                for (int j = 0; j < 8; j++)
                    FFMA2(acc[mp][j], a[mp], d[j]);
        }
    }

    float* Cout = (nb < 2) ? g_kxW : g_xW1;
    const int colbase = (nb & 1) * 128;
#pragma unroll
    for (int mp = 0; mp < 8; mp++) {
        size_t r = (size_t)rb * 128 + ty * 16 + 2 * mp;
        float4 v;
        v.x = lo32(acc[mp][0]); v.y = lo32(acc[mp][1]); v.z = lo32(acc[mp][2]); v.w = lo32(acc[mp][3]);
        *(float4*)&Cout[r * 256 + colbase + tx * 4] = v;
        v.x = lo32(acc[mp][4]); v.y = lo32(acc[mp][5]); v.z = lo32(acc[mp][6]); v.w = lo32(acc[mp][7]);
        *(float4*)&Cout[r * 256 + colbase + 64 + tx * 4] = v;
        v.x = hi32(acc[mp][0]); v.y = hi32(acc[mp][1]); v.z = hi32(acc[mp][2]); v.w = hi32(acc[mp][3]);
        *(float4*)&Cout[(r + 1) * 256 + colbase + tx * 4] = v;
        v.x = hi32(acc[mp][4]); v.y = hi32(acc[mp][5]); v.z = hi32(acc[mp][6]); v.w = hi32(acc[mp][7]);
        *(float4*)&Cout[(r + 1) * 256 + colbase + 64 + tx * 4] = v;
    }
}

// ---------------- kscore GEMV: one warp per row ----------------
__global__ void k_kscore(const float* __restrict__ X) {
    int warp = threadIdx.x >> 5, lane = threadIdx.x & 31;
    size_t row = (size_t)blockIdx.x * 8 + warp;
    const float4* xp = reinterpret_cast<const float4*>(X + row * 256);
    const float4* wp = reinterpret_cast<const float4*>(g_wk1);
    float4 a = xp[lane], w = wp[lane];
    float d = a.x * w.x + a.y * w.y + a.z * w.z + a.w * w.w;
    float4 a2 = xp[lane + 32], w2 = wp[lane + 32];
    d += a2.x * w2.x + a2.y * w2.y + a2.z * w2.z + a2.w * w2.w;
#pragma unroll
    for (int off = 16; off; off >>= 1) d += __shfl_down_sync(0xFFFFFFFFu, d, off);
    if (lane == 0) g_kscore[row] = d + g_scalars[1];
}

// ---------------- recurrent scan v4: 2 independent warps per CTA (single wave) --
// 128 CTAs x 64 threads; warp w handles pair = 2*cta + w -> (b = pair>>2, i = pair&3)
__global__ void __launch_bounds__(64) k_recur3() {
    __shared__ __align__(16) float4 sbuf[2][4][324];
    const int w = threadIdx.x >> 5;
    const int lane = threadIdx.x & 31;
    const int pair = blockIdx.x * 2 + w;
    const int b = pair >> 2, i = pair & 3;

    float4 wva = *(const float4*)(g_w2v + lane * 4);
    float4 wvb = *(const float4*)(g_w2v + 128 + lane * 4);
    float4 cba, cbb;
    {
        float4 bka = *(const float4*)(g_bias + lane * 4);
        float4 bkb = *(const float4*)(g_bias + 128 + lane * 4);
        float4 bxa = *(const float4*)(g_bias + 256 + lane * 4);
        float4 bxb = *(const float4*)(g_bias + 256 + 128 + lane * 4);
        cba.x = bka.x + bxa.x; cba.y = bka.y + bxa.y; cba.z = bka.z + bxa.z; cba.w = bka.w + bxa.w;
        cbb.x = bkb.x + bxb.x; cbb.y = bkb.y + bxb.y; cbb.z = bkb.z + bxb.z; cbb.w = bkb.w + bxb.w;
    }
    const float c2 = g_scalars[2];
    float qs = g_scalars[0];

    auto issue = [&](int t, int s) {
        const float4* kxg = (const float4*)(g_kxW + ((size_t)(b * 512 + t) * 4) * 256);
        const float4* sxg = (const float4*)(g_xW1 + ((size_t)((b * 512 + t) * 4 + i)) * 256);
        float4* st = sbuf[w][s];
#pragma unroll
        for (int u = 0; u < 8; u++) cpa16(&st[lane + u * 32], kxg + lane + u * 32);
        cpa16(&st[256 + lane * 2], sxg + lane * 2);
        cpa16(&st[256 + lane * 2 + 1], sxg + lane * 2 + 1);
        if (lane == 0) cpa16(&st[320], g_kscore + (size_t)(b * 512 + t) * 4);
        asm volatile("cp.async.commit_group;" ::: "memory");
    };

    issue(0, 0); issue(1, 1); issue(2, 2); issue(3, 3);

    for (int t = 0; t < 512; t++) {
        const int s = t & 3;
        asm volatile("cp.async.wait_group 3;" ::: "memory");
        __syncwarp();

        const float4* st = sbuf[w][s];
        float4 k0a = st[lane],        k0b = st[32 + lane];
        float4 k1a = st[64 + lane],   k1b = st[96 + lane];
        float4 k2a = st[128 + lane],  k2b = st[160 + lane];
        float4 k3a = st[192 + lane],  k3b = st[224 + lane];
        float4 sxa = st[256 + lane],  sxb = st[288 + lane];
        float4 ks4 = st[320];
        __syncwarp();

        // prefetch t+4 into this (now register-held) slot before compute
        if (t + 4 < 512) issue(t + 4, s);

        // softmax over tanh scores; tanh in [-1,1] so no max-subtract needed
        float e0 = __expf(tanh_ap(qs + ks4.x));
        float e1 = __expf(tanh_ap(qs + ks4.y));
        float e2 = __expf(tanh_ap(qs + ks4.z));
        float e3 = __expf(tanh_ap(qs + ks4.w));
        float inv = rcp_ap((e0 + e1) + (e2 + e3));
        float p0 = e0 * inv, p1 = e1 * inv, p2 = e2 * inv, p3 = e3 * inv;

        float4 ra, rb;
        ra.x = fmaxf(sxa.x + cba.x + (p0 * k0a.x + p1 * k1a.x) + (p2 * k2a.x + p3 * k3a.x), 0.f);
        ra.y = fmaxf(sxa.y + cba.y + (p0 * k0a.y + p1 * k1a.y) + (p2 * k2a.y + p3 * k3a.y), 0.f);
        ra.z = fmaxf(sxa.z + cba.z + (p0 * k0a.z + p1 * k1a.z) + (p2 * k2a.z + p3 * k3a.z), 0.f);
        ra.w = fmaxf(sxa.w + cba.w + (p0 * k0a.w + p1 * k1a.w) + (p2 * k2a.w + p3 * k3a.w), 0.f);
        rb.x = fmaxf(sxb.x + cbb.x + (p0 * k0b.x + p1 * k1b.x) + (p2 * k2b.x + p3 * k3b.x), 0.f);
        rb.y = fmaxf(sxb.y + cbb.y + (p0 * k0b.y + p1 * k1b.y) + (p2 * k2b.y + p3 * k3b.y), 0.f);
        rb.z = fmaxf(sxb.z + cbb.z + (p0 * k0b.z + p1 * k1b.z) + (p2 * k2b.z + p3 * k3b.z), 0.f);
        rb.w = fmaxf(sxb.w + cbb.w + (p0 * k0b.w + p1 * k1b.w) + (p2 * k2b.w + p3 * k3b.w), 0.f);

        float dA = (wva.x * ra.x + wva.y * ra.y) + (wva.z * ra.z + wva.w * ra.w);
        float dB = (wvb.x * rb.x + wvb.y * rb.y) + (wvb.z * rb.z + wvb.w * rb.w);
        float dot = dA + dB;
#pragma unroll
        for (int off = 16; off; off >>= 1) dot += __shfl_xor_sync(0xFFFFFFFFu, dot, off);
        qs = c2 + dot;

        if (t == 511) {
            float* dst = g_h1 + (size_t)(b * 4 + i) * 256;
            *(float4*)(dst + lane * 4) = ra;
            *(float4*)(dst + 128 + lane * 4) = rb;
        }
    }
}

// ---------------- epilogue ----------------
__global__ void k_hfinal(const float* __restrict__ W2, const float* __restrict__ b2,
                         float* __restrict__ out) {
    int r = blockIdx.x, tid = threadIdx.x;
    __shared__ float sh[256];
    sh[tid] = g_h1[r * 256 + tid];
    __syncthreads();
    float acc = b2[tid];
    for (int h = 0; h < 256; h++) acc += sh[h] * W2[h * 256 + tid];
    g_hidden[r * 256 + tid] = acc;
    out[192 + r * 256 + tid] = acc;
}

__global__ void k_logits(const float* __restrict__ Wo, const float* __restrict__ bo,
                         float* __restrict__ out) {
    int bidx = blockIdx.x, tid = threadIdx.x, lane = tid & 31, wid = tid >> 5;
    __shared__ float red[4][3];
    float p0 = 0.f, p1 = 0.f, p2 = 0.f;
    for (int k = tid; k < 1024; k += 128) {
        float h = g_hidden[bidx * 1024 + k];
        p0 += h * Wo[k * 3 + 0];
        p1 += h * Wo[k * 3 + 1];
        p2 += h * Wo[k * 3 + 2];
    }
#pragma unroll
    for (int off = 16; off; off >>= 1) {
        p0 += __shfl_down_sync(0xFFFFFFFFu, p0, off);
        p1 += __shfl_down_sync(0xFFFFFFFFu, p1, off);
        p2 += __shfl_down_sync(0xFFFFFFFFu, p2, off);
    }
    if (lane == 0) { red[wid][0] = p0; red[wid][1] = p1; red[wid][2] = p2; }
    __syncthreads();
    if (tid == 0) {
        float l0 = bo[0], l1 = bo[1], l2 = bo[2];
        for (int w = 0; w < 4; w++) { l0 += red[w][0]; l1 += red[w][1]; l2 += red[w][2]; }
        float m = fmaxf(l0, fmaxf(l1, l2));
        float lse = m + logf(expf(l0 - m) + expf(l1 - m) + expf(l2 - m));
        out[bidx * 3 + 0] = l0 - lse;
        out[bidx * 3 + 1] = l1 - lse;
        out[bidx * 3 + 2] = l2 - lse;
    }
}

// ---------------- launch ----------------
extern "C" void kernel_launch(void* const* d_in, const int* in_sizes, int n_in,
                              void* d_out, int out_size) {
    const float* x     = (const float*)d_in[0];
    const float* Wk    = (const float*)d_in[1];
    const float* bk    = (const float*)d_in[2];
    const float* Wq    = (const float*)d_in[3];
    const float* bq    = (const float*)d_in[4];
    const float* w_mlp = (const float*)d_in[5];
    const float* Wproj = (const float*)d_in[6];
    const float* bproj = (const float*)d_in[7];
    const float* W1    = (const float*)d_in[8];
    const float* b1    = (const float*)d_in[9];
    const float* W2    = (const float*)d_in[10];
    const float* b2    = (const float*)d_in[11];
    const float* Wo    = (const float*)d_in[12];
    const float* bo    = (const float*)d_in[13];
    float* out = (float*)d_out;

    k_setup1<<<257, 32>>>(Wk, bk, Wq, bq, w_mlp);
    k_wcomb<<<256, 256>>>(Wproj, W1);
    k_wkc<<<257, 256>>>(Wk, W1, bk, b1, bproj);
    k_w2v<<<257, 32>>>(W2, b2);
    k_kscore<<<16384, 256>>>(x);
    k_gemm2<<<dim3(4, 1024), 128>>>(x);
    k_recur3<<<128, 64>>>();
    k_hfinal<<<256, 256>>>(W2, b2, out);
    k_logits<<<64, 128>>>(Wo, bo, out);
}